// round 5
// baseline (speedup 1.0000x reference)
#include <cuda_runtime.h>
#include <cuda_bf16.h>
#include <cstdint>

#define N_NODES 100000
#define N_EDGES 1600000
#define IN_F 512
#define HID_F 128
#define N_CLS 64

// ---------------- scratch (device globals; referenced ONLY inside kernels) --
__device__ float g_xw1[(size_t)N_NODES * HID_F];   // x@w1+b1
__device__ float g_h[(size_t)N_NODES * HID_F];     // relu(A @ xw1)
__device__ float g_hw2[(size_t)N_NODES * N_CLS];   // h@w2+b2
__device__ int   g_deg[N_NODES];
__device__ int   g_rowptr[N_NODES + 1];
__device__ int   g_cursor[N_NODES];
__device__ int   g_scol[N_EDGES];
__device__ float g_sval[N_EDGES];

// ---------------- CSR build --------------------------------------------------
__global__ void zero_deg_kernel() {
    int i = blockIdx.x * blockDim.x + threadIdx.x;
    if (i < N_NODES) g_deg[i] = 0;
}

__global__ void hist_kernel(const int* __restrict__ row) {
    int e = blockIdx.x * blockDim.x + threadIdx.x;
    if (e < N_EDGES) atomicAdd(&g_deg[row[e]], 1);
}

// single-block exclusive scan over N_NODES degrees -> rowptr, cursor
__global__ void scan_kernel() {
    const int T = 1024;
    __shared__ int sh[T];
    int tid = threadIdx.x;
    const int chunk = (N_NODES + T - 1) / T;  // 98
    int start = tid * chunk;
    int end = min(start + chunk, N_NODES);
    int s = 0;
    for (int i = start; i < end; i++) s += g_deg[i];
    sh[tid] = s;
    __syncthreads();
    for (int off = 1; off < T; off <<= 1) {
        int v = (tid >= off) ? sh[tid - off] : 0;
        __syncthreads();
        sh[tid] += v;
        __syncthreads();
    }
    int run = sh[tid] - s;  // exclusive prefix
    for (int i = start; i < end; i++) {
        int d = g_deg[i];
        g_rowptr[i] = run;
        g_cursor[i] = run;
        run += d;
    }
    if (tid == T - 1) g_rowptr[N_NODES] = sh[T - 1];
}

__global__ void scatter_kernel(const int* __restrict__ row,
                               const int* __restrict__ col,
                               const float* __restrict__ val) {
    int e = blockIdx.x * blockDim.x + threadIdx.x;
    if (e >= N_EDGES) return;
    int r = row[e];
    int p = atomicAdd(&g_cursor[r], 1);
    g_scol[p] = col[e];
    g_sval[p] = val[e];
}

// ---------------- GEMM1 (tf32 tensor cores, 2-stage cp.async) ---------------
// C[128 x 128] per block, K=512.  256 threads = 8 warps (2 m x 4 n).
// Raw fp32 bits fed to tf32 MMA (truncation) — no cvt, enables cp.async.
__device__ __forceinline__ void cp_async16(uint32_t smem_addr, const void* gptr, int src_bytes) {
    asm volatile("cp.async.cg.shared.global [%0], [%1], 16, %2;"
                 :: "r"(smem_addr), "l"(gptr), "r"(src_bytes));
}

__global__ __launch_bounds__(256) void gemm1_tf32_kernel(const float* __restrict__ A,
                                                         const float* __restrict__ B,
                                                         const float* __restrict__ bias) {
    const int K = IN_F;                     // 512
    __shared__ uint32_t As[2][128][20];     // [m][k], BK=16 padded to 20
    __shared__ uint32_t Bs[2][16][136];     // [k][n], BN=128 padded to 136
    int tid = threadIdx.x;
    int wid = tid >> 5, lane = tid & 31;
    int grp = lane >> 2, q = lane & 3;
    int warp_m = wid >> 2;                  // 0..1
    int warp_n = wid & 3;                   // 0..3
    int m_warp = warp_m * 64;
    int n_warp = warp_n * 32;
    int block_row = blockIdx.x * 128;

    float acc[4][4][4];
#pragma unroll
    for (int mt = 0; mt < 4; mt++)
#pragma unroll
        for (int nt = 0; nt < 4; nt++)
#pragma unroll
            for (int i = 0; i < 4; i++) acc[mt][nt][i] = 0.f;

    // A-tile map: 2 chunks/thread; row = tid>>2 (+64), aj = (tid&3)*4
    int ar = tid >> 2;                      // 0..63
    int aj = (tid & 3) << 2;                // 0,4,8,12
    int arow0 = block_row + ar, arow1 = block_row + ar + 64;
    const float* aptr0 = A + (size_t)arow0 * K + aj;
    const float* aptr1 = A + (size_t)arow1 * K + aj;
    int asz0 = (arow0 < N_NODES) ? 16 : 0;  // zfill out-of-range rows
    int asz1 = (arow1 < N_NODES) ? 16 : 0;
    // B-tile map: k = wid (+8), col = (tid&31)*4
    int bc = (tid & 31) << 2;
    const float* bptr0 = B + (size_t)wid * HID_F + bc;
    const float* bptr1 = B + (size_t)(wid + 8) * HID_F + bc;

    uint32_t sa0[2], sa1[2], sb0[2], sb1[2];
#pragma unroll
    for (int s = 0; s < 2; s++) {
        sa0[s] = (uint32_t)__cvta_generic_to_shared(&As[s][ar][aj]);
        sa1[s] = (uint32_t)__cvta_generic_to_shared(&As[s][ar + 64][aj]);
        sb0[s] = (uint32_t)__cvta_generic_to_shared(&Bs[s][wid][bc]);
        sb1[s] = (uint32_t)__cvta_generic_to_shared(&Bs[s][wid + 8][bc]);
    }

    const int NT = K / 16;                  // 32
    // prologue: stage 0, k0 = 0
    cp_async16(sa0[0], aptr0, asz0);
    cp_async16(sa1[0], aptr1, asz1);
    cp_async16(sb0[0], bptr0, 16);
    cp_async16(sb1[0], bptr1, 16);
    asm volatile("cp.async.commit_group;");

    for (int ki = 0; ki < NT; ki++) {
        asm volatile("cp.async.wait_group 0;");
        __syncthreads();
        if (ki + 1 < NT) {
            int st = (ki + 1) & 1;
            int k0 = (ki + 1) * 16;
            cp_async16(sa0[st], aptr0 + k0, asz0);
            cp_async16(sa1[st], aptr1 + k0, asz1);
            cp_async16(sb0[st], bptr0 + (size_t)k0 * HID_F, 16);
            cp_async16(sb1[st], bptr1 + (size_t)k0 * HID_F, 16);
            asm volatile("cp.async.commit_group;");
        }
        int cs = ki & 1;
#pragma unroll
        for (int ks = 0; ks < 2; ks++) {
            int kb = ks * 8;
            uint32_t afr[4][4], bfr[4][2];
#pragma unroll
            for (int mt = 0; mt < 4; mt++) {
                int m0 = m_warp + mt * 16;
                afr[mt][0] = As[cs][m0 + grp][kb + q];
                afr[mt][1] = As[cs][m0 + grp + 8][kb + q];
                afr[mt][2] = As[cs][m0 + grp][kb + q + 4];
                afr[mt][3] = As[cs][m0 + grp + 8][kb + q + 4];
            }
#pragma unroll
            for (int nt = 0; nt < 4; nt++) {
                int n0 = n_warp + nt * 8;
                bfr[nt][0] = Bs[cs][kb + q][n0 + grp];
                bfr[nt][1] = Bs[cs][kb + q + 4][n0 + grp];
            }
#pragma unroll
            for (int mt = 0; mt < 4; mt++)
#pragma unroll
                for (int nt = 0; nt < 4; nt++)
                    asm volatile(
                        "mma.sync.aligned.m16n8k8.row.col.f32.tf32.tf32.f32 "
                        "{%0,%1,%2,%3}, {%4,%5,%6,%7}, {%8,%9}, {%0,%1,%2,%3};"
                        : "+f"(acc[mt][nt][0]), "+f"(acc[mt][nt][1]),
                          "+f"(acc[mt][nt][2]), "+f"(acc[mt][nt][3])
                        : "r"(afr[mt][0]), "r"(afr[mt][1]),
                          "r"(afr[mt][2]), "r"(afr[mt][3]),
                          "r"(bfr[nt][0]), "r"(bfr[nt][1]));
        }
    }

    // writeback with bias
#pragma unroll
    for (int mt = 0; mt < 4; mt++) {
        int r0 = block_row + m_warp + mt * 16 + grp;
        int r1 = r0 + 8;
#pragma unroll
        for (int nt = 0; nt < 4; nt++) {
            int c = n_warp + nt * 8 + q * 2;
            float bv0 = __ldg(bias + c), bv1 = __ldg(bias + c + 1);
            if (r0 < N_NODES) {
                float2 o = make_float2(acc[mt][nt][0] + bv0, acc[mt][nt][1] + bv1);
                *(float2*)(g_xw1 + (size_t)r0 * HID_F + c) = o;
            }
            if (r1 < N_NODES) {
                float2 o = make_float2(acc[mt][nt][2] + bv0, acc[mt][nt][3] + bv1);
                *(float2*)(g_xw1 + (size_t)r1 * HID_F + c) = o;
            }
        }
    }
}

// ---------------- SpMM (CSR, warp per row), F=128, fused relu, unroll x2 ----
__global__ void spmm128_relu_kernel() {
    int warp = (blockIdx.x * blockDim.x + threadIdx.x) >> 5;
    if (warp >= N_NODES) return;
    int lane = threadIdx.x & 31;
    int beg = g_rowptr[warp], end = g_rowptr[warp + 1];
    float4 acc = make_float4(0.f, 0.f, 0.f, 0.f);
    int e = beg;
    for (; e + 2 <= end; e += 2) {
        int c0 = g_scol[e], c1 = g_scol[e + 1];
        float v0 = g_sval[e], v1 = g_sval[e + 1];
        float4 a = ((const float4*)(g_xw1 + (size_t)c0 * HID_F))[lane];
        float4 b = ((const float4*)(g_xw1 + (size_t)c1 * HID_F))[lane];
        acc.x += v0 * a.x + v1 * b.x;
        acc.y += v0 * a.y + v1 * b.y;
        acc.z += v0 * a.z + v1 * b.z;
        acc.w += v0 * a.w + v1 * b.w;
    }
    if (e < end) {
        int c0 = g_scol[e];
        float v0 = g_sval[e];
        float4 a = ((const float4*)(g_xw1 + (size_t)c0 * HID_F))[lane];
        acc.x += v0 * a.x;
        acc.y += v0 * a.y;
        acc.z += v0 * a.z;
        acc.w += v0 * a.w;
    }
    acc.x = fmaxf(acc.x, 0.f);
    acc.y = fmaxf(acc.y, 0.f);
    acc.z = fmaxf(acc.z, 0.f);
    acc.w = fmaxf(acc.w, 0.f);
    ((float4*)(g_h + (size_t)warp * HID_F))[lane] = acc;
}

// ---------------- GEMM2: g_h [N,128] @ w2 [128,64] + b2 -> g_hw2 ------------
__global__ __launch_bounds__(256) void gemm2_kernel(const float* __restrict__ W2,
                                                    const float* __restrict__ b2) {
    __shared__ float sw[HID_F * N_CLS];   // 32 KB
    __shared__ float shh[4][HID_F];
    int tid = threadIdx.x;
    for (int i = tid; i < HID_F * N_CLS; i += 256) sw[i] = W2[i];
    float bias = b2[tid & 63];
    int rl = tid >> 6;  // 0..3
    int j = tid & 63;
    __syncthreads();
    for (int row0 = blockIdx.x * 4; row0 < N_NODES; row0 += gridDim.x * 4) {
        for (int i = tid; i < 4 * HID_F; i += 256) {
            int r = row0 + (i >> 7);
            shh[i >> 7][i & 127] = (r < N_NODES) ? g_h[(size_t)r * HID_F + (i & 127)] : 0.f;
        }
        __syncthreads();
        float acc = 0.f;
#pragma unroll 8
        for (int k = 0; k < HID_F; k++) acc += shh[rl][k] * sw[k * N_CLS + j];
        int r = row0 + rl;
        if (r < N_NODES) g_hw2[(size_t)r * N_CLS + j] = acc + bias;
        __syncthreads();
    }
}

// ---------------- SpMM F=64 (final output; reads g_hw2), unroll x2 ----------
__global__ void spmm64_kernel(float* __restrict__ dst) {
    int warp = (blockIdx.x * blockDim.x + threadIdx.x) >> 5;
    if (warp >= N_NODES) return;
    int lane = threadIdx.x & 31;
    int beg = g_rowptr[warp], end = g_rowptr[warp + 1];
    float2 acc = make_float2(0.f, 0.f);
    int e = beg;
    for (; e + 2 <= end; e += 2) {
        int c0 = g_scol[e], c1 = g_scol[e + 1];
        float v0 = g_sval[e], v1 = g_sval[e + 1];
        float2 a = ((const float2*)(g_hw2 + (size_t)c0 * N_CLS))[lane];
        float2 b = ((const float2*)(g_hw2 + (size_t)c1 * N_CLS))[lane];
        acc.x += v0 * a.x + v1 * b.x;
        acc.y += v0 * a.y + v1 * b.y;
    }
    if (e < end) {
        int c0 = g_scol[e];
        float v0 = g_sval[e];
        float2 a = ((const float2*)(g_hw2 + (size_t)c0 * N_CLS))[lane];
        acc.x += v0 * a.x;
        acc.y += v0 * a.y;
    }
    ((float2*)(dst + (size_t)warp * N_CLS))[lane] = acc;
}

// ---------------- launch -----------------------------------------------------
extern "C" void kernel_launch(void* const* d_in, const int* in_sizes, int n_in,
                              void* d_out, int out_size) {
    // Identify inputs by element count (robust to metadata ordering).
    const float* x = nullptr; const float* w1 = nullptr; const float* b1 = nullptr;
    const float* w2 = nullptr; const float* b2 = nullptr;
    const void* edge_arrs[3] = {nullptr, nullptr, nullptr};
    int n_edge_arrs = 0;
    for (int i = 0; i < n_in; i++) {
        long sz = in_sizes[i];
        if (sz == (long)N_NODES * IN_F)      x  = (const float*)d_in[i];
        else if (sz == IN_F * HID_F)         w1 = (const float*)d_in[i];
        else if (sz == HID_F * N_CLS)        w2 = (const float*)d_in[i];
        else if (sz == HID_F)                b1 = (const float*)d_in[i];
        else if (sz == N_CLS)                b2 = (const float*)d_in[i];
        else if (sz == N_EDGES && n_edge_arrs < 3) edge_arrs[n_edge_arrs++] = d_in[i];
    }
    const int*   row = (const int*)edge_arrs[0];
    const int*   col = (const int*)edge_arrs[1];
    const float* val = (const float*)edge_arrs[2];
    float* out = (float*)d_out;

    // One-time stream/event creation (outside capture on first call).
    static cudaStream_t s_side = nullptr;
    static cudaEvent_t ev_fork = nullptr, ev_join = nullptr;
    if (s_side == nullptr) {
        cudaStreamCreate(&s_side);
        cudaEventCreateWithFlags(&ev_fork, cudaEventDisableTiming);
        cudaEventCreateWithFlags(&ev_join, cudaEventDisableTiming);
    }

    // Fork: CSR build (L2/atomic-bound) overlaps gemm1 (tensor-bound).
    cudaEventRecord(ev_fork, 0);
    cudaStreamWaitEvent(s_side, ev_fork, 0);
    zero_deg_kernel<<<(N_NODES + 511) / 512, 512, 0, s_side>>>();
    hist_kernel<<<(N_EDGES + 511) / 512, 512, 0, s_side>>>(row);
    scan_kernel<<<1, 1024, 0, s_side>>>();
    scatter_kernel<<<(N_EDGES + 511) / 512, 512, 0, s_side>>>(row, col, val);
    cudaEventRecord(ev_join, s_side);

    gemm1_tf32_kernel<<<(N_NODES + 127) / 128, 256>>>(x, w1, b1);

    // Join: spmm128 needs both gemm1 output and CSR.
    cudaStreamWaitEvent(0, ev_join, 0);
    spmm128_relu_kernel<<<(N_NODES * 32 + 255) / 256, 256>>>();

    gemm2_kernel<<<2048, 256>>>(w2, b2);
    spmm64_kernel<<<(N_NODES * 32 + 255) / 256, 256>>>(out);
}